// round 1
// baseline (speedup 1.0000x reference)
#include <cuda_runtime.h>
#include <cstdint>

#define N_MAX   50000
#define OUT     128
#define EDIM    64

// ---------------- device scratch (no cudaMalloc allowed) ----------------
__device__ __align__(16) float g_W1[128 * 128];   // Wx @ Wm_top   [128,128]
__device__ __align__(16) float g_W2[64 * 128];    // We @ Wm_bot   [64,128]
__device__ __align__(16) float g_c[128];          // fused bias
__device__ __align__(16) float g_A[(size_t)N_MAX * OUT];    // x @ W1
__device__ __align__(16) float g_agg[(size_t)N_MAX * OUT];  // scatter target
__device__ int g_is64;

// ---------------- f32x2 helpers ----------------
__device__ __forceinline__ unsigned long long pk2(float x, float y) {
    unsigned long long r;
    asm("mov.b64 %0, {%1, %2};" : "=l"(r) : "f"(x), "f"(y));
    return r;
}
__device__ __forceinline__ void upk2(unsigned long long v, float& x, float& y) {
    asm("mov.b64 {%0, %1}, %2;" : "=f"(x), "=f"(y) : "l"(v));
}
__device__ __forceinline__ void ffma2(unsigned long long& acc, unsigned long long w,
                                      unsigned long long a) {
    asm("fma.rn.f32x2 %0, %1, %2, %0;" : "+l"(acc) : "l"(w), "l"(a));
}

// ---------------- detect int64 vs int32 edge_index ----------------
// int64 little-endian indices < 2^31 have zero high words at all odd 32-bit slots.
__global__ void detect_kernel(const int* __restrict__ idx) {
    if (blockIdx.x == 0 && threadIdx.x == 0) {
        int ok = 1;
        for (int i = 1; i < 64; i += 2)
            if (idx[i] != 0) ok = 0;
        g_is64 = ok;
    }
}

// ---------------- fold the three weight matrices ----------------
// blocks 0..127  : W1 row b   = Wx[b,:]  @ Wm[0:128,:]
// blocks 128..191: W2 row b-128 = We[b-128,:] @ Wm[128:256,:]
// block 192      : c = bm + bx @ Wm[0:128,:] + be @ Wm[128:256,:]
__global__ void prep_kernel(const float* __restrict__ Wx, const float* __restrict__ bx,
                            const float* __restrict__ We, const float* __restrict__ be,
                            const float* __restrict__ Wm, const float* __restrict__ bm) {
    __shared__ float row[128];
    __shared__ float row2[128];
    const int b = blockIdx.x;
    const int j = threadIdx.x;  // 128 threads
    if (b < 128) {
        row[j] = Wx[b * 128 + j];
        __syncthreads();
        float s = 0.f;
#pragma unroll 8
        for (int k = 0; k < 128; k++) s = fmaf(row[k], Wm[k * 128 + j], s);
        g_W1[b * 128 + j] = s;
    } else if (b < 192) {
        const int i = b - 128;
        row[j] = We[i * 128 + j];
        __syncthreads();
        float s = 0.f;
#pragma unroll 8
        for (int k = 0; k < 128; k++) s = fmaf(row[k], Wm[(128 + k) * 128 + j], s);
        g_W2[i * 128 + j] = s;
    } else {
        row[j] = bx[j];
        row2[j] = be[j];
        __syncthreads();
        float s = bm[j];
#pragma unroll 8
        for (int k = 0; k < 128; k++) {
            s = fmaf(row[k], Wm[k * 128 + j], s);
            s = fmaf(row2[k], Wm[(128 + k) * 128 + j], s);
        }
        g_c[j] = s;
    }
}

// ---------------- zero the aggregation buffer ----------------
__global__ void zero_kernel(int n4) {
    int i = blockIdx.x * blockDim.x + threadIdx.x;
    const int stride = gridDim.x * blockDim.x;
    float4 z = make_float4(0.f, 0.f, 0.f, 0.f);
    for (; i < n4; i += stride) reinterpret_cast<float4*>(g_agg)[i] = z;
}

// ---------------- node GEMM: A = x @ W1 ----------------
// one warp computes 4 rows at a time; W1 (64 KB) in dynamic smem.
__global__ void __launch_bounds__(256) node_kernel(const float* __restrict__ x, int N) {
    extern __shared__ float w1s[];  // 128*128 floats
    const int tid = threadIdx.x;
    for (int i = tid; i < 128 * 128; i += blockDim.x) w1s[i] = g_W1[i];
    __syncthreads();

    const int lane = tid & 31;
    const int gw = (blockIdx.x * blockDim.x + tid) >> 5;
    const int nw = (gridDim.x * blockDim.x) >> 5;
    constexpr int T = 4;

    for (int base = gw * T; base < N; base += nw * T) {
        const int cnt = min(T, N - base);
        float a[T][4];
#pragma unroll
        for (int t = 0; t < T; t++) {
            const int r = base + (t < cnt ? t : 0);
#pragma unroll
            for (int q = 0; q < 4; q++) a[t][q] = x[(size_t)r * 128 + q * 32 + lane];
        }
        unsigned long long acc0[T], acc1[T];
#pragma unroll
        for (int t = 0; t < T; t++) { acc0[t] = 0ull; acc1[t] = 0ull; }

#pragma unroll
        for (int q = 0; q < 4; q++) {
#pragma unroll 8
            for (int kk = 0; kk < 32; kk++) {
                const int k = q * 32 + kk;
                const float4 w = *reinterpret_cast<const float4*>(&w1s[k * 128 + lane * 4]);
                const unsigned long long w01 = pk2(w.x, w.y);
                const unsigned long long w23 = pk2(w.z, w.w);
#pragma unroll
                for (int t = 0; t < T; t++) {
                    const float av = __shfl_sync(0xffffffffu, a[t][q], kk);
                    const unsigned long long aa = pk2(av, av);
                    ffma2(acc0[t], w01, aa);
                    ffma2(acc1[t], w23, aa);
                }
            }
        }
#pragma unroll
        for (int t = 0; t < T; t++) {
            if (t < cnt) {
                float o0, o1, o2, o3;
                upk2(acc0[t], o0, o1);
                upk2(acc1[t], o2, o3);
                *reinterpret_cast<float4*>(&g_A[(size_t)(base + t) * 128 + lane * 4]) =
                    make_float4(o0, o1, o2, o3);
            }
        }
    }
}

// ---------------- edge kernel: msg + scatter ----------------
// one warp handles 8 edges per sweep: B = ea @ W2 (f32x2), gather A[src] (L2),
// leaky_relu, red.global.add.v4 into g_agg[dst].
__global__ void __launch_bounds__(256) edge_kernel(const float* __restrict__ ea,
                                                   const int* __restrict__ idx, int E) {
    __shared__ float w2s[EDIM * OUT];  // 32 KB
    __shared__ float cs[OUT];
    const int tid = threadIdx.x;
    for (int i = tid; i < EDIM * OUT; i += blockDim.x) w2s[i] = g_W2[i];
    if (tid < OUT) cs[tid] = g_c[tid];
    __syncthreads();

    const int lane = tid & 31;
    const float4 cv = *reinterpret_cast<const float4*>(&cs[lane * 4]);
    const int is64 = g_is64;
    const int gw = (blockIdx.x * blockDim.x + tid) >> 5;
    const int nw = (gridDim.x * blockDim.x) >> 5;
    constexpr int T = 8;

    for (long long base = (long long)gw * T; base < E; base += (long long)nw * T) {
        const int cnt = (int)min((long long)T, (long long)E - base);
        float a0[T], a1[T];
        int sidx[T], didx[T];
#pragma unroll
        for (int t = 0; t < T; t++) {
            const long long e = base + (t < cnt ? t : 0);
            const long long so = is64 ? 2 * e : e;
            const long long dof = is64 ? 2 * (e + E) : (e + E);
            sidx[t] = idx[so];
            didx[t] = idx[dof];
            a0[t] = ea[e * 64 + lane];
            a1[t] = ea[e * 64 + 32 + lane];
        }

        unsigned long long acc0[T], acc1[T];
#pragma unroll
        for (int t = 0; t < T; t++) { acc0[t] = 0ull; acc1[t] = 0ull; }

#pragma unroll 8
        for (int k = 0; k < 32; k++) {
            const float4 w = *reinterpret_cast<const float4*>(&w2s[k * 128 + lane * 4]);
            const unsigned long long w01 = pk2(w.x, w.y);
            const unsigned long long w23 = pk2(w.z, w.w);
#pragma unroll
            for (int t = 0; t < T; t++) {
                const float av = __shfl_sync(0xffffffffu, a0[t], k);
                const unsigned long long aa = pk2(av, av);
                ffma2(acc0[t], w01, aa);
                ffma2(acc1[t], w23, aa);
            }
        }
#pragma unroll 8
        for (int k = 0; k < 32; k++) {
            const float4 w = *reinterpret_cast<const float4*>(&w2s[(k + 32) * 128 + lane * 4]);
            const unsigned long long w01 = pk2(w.x, w.y);
            const unsigned long long w23 = pk2(w.z, w.w);
#pragma unroll
            for (int t = 0; t < T; t++) {
                const float av = __shfl_sync(0xffffffffu, a1[t], k);
                const unsigned long long aa = pk2(av, av);
                ffma2(acc0[t], w01, aa);
                ffma2(acc1[t], w23, aa);
            }
        }

#pragma unroll
        for (int t = 0; t < T; t++) {
            if (t < cnt) {
                const float4 av = __ldg(reinterpret_cast<const float4*>(
                    &g_A[(size_t)sidx[t] * 128 + lane * 4]));
                float o0, o1, o2, o3;
                upk2(acc0[t], o0, o1);
                upk2(acc1[t], o2, o3);
                o0 += av.x + cv.x;
                o1 += av.y + cv.y;
                o2 += av.z + cv.z;
                o3 += av.w + cv.w;
                o0 = (o0 > 0.f) ? o0 : 0.01f * o0;
                o1 = (o1 > 0.f) ? o1 : 0.01f * o1;
                o2 = (o2 > 0.f) ? o2 : 0.01f * o2;
                o3 = (o3 > 0.f) ? o3 : 0.01f * o3;
                float* p = &g_agg[(size_t)didx[t] * 128 + lane * 4];
                asm volatile("red.global.add.v4.f32 [%0], {%1, %2, %3, %4};" ::
                                 "l"(p), "f"(o0), "f"(o1), "f"(o2), "f"(o3)
                             : "memory");
            }
        }
    }
}

// ---------------- epilogue: out = sigmoid(agg) * relu(beta) ----------------
__global__ void final_kernel(float* __restrict__ out, const float* __restrict__ beta,
                             int n4) {
    float b = beta[0];
    b = (b > 0.f) ? b : 0.f;
    int i = blockIdx.x * blockDim.x + threadIdx.x;
    const int stride = gridDim.x * blockDim.x;
    for (; i < n4; i += stride) {
        float4 v = reinterpret_cast<const float4*>(g_agg)[i];
        v.x = b / (1.f + __expf(-v.x));
        v.y = b / (1.f + __expf(-v.y));
        v.z = b / (1.f + __expf(-v.z));
        v.w = b / (1.f + __expf(-v.w));
        reinterpret_cast<float4*>(out)[i] = v;
    }
}

// ---------------- launch ----------------
extern "C" void kernel_launch(void* const* d_in, const int* in_sizes, int n_in,
                              void* d_out, int out_size) {
    const float* x    = (const float*)d_in[0];
    const int*   idx  = (const int*)d_in[1];   // int32 or int64 raw words
    const float* ea   = (const float*)d_in[2];
    const float* Wx   = (const float*)d_in[3];
    const float* bx   = (const float*)d_in[4];
    const float* We   = (const float*)d_in[5];
    const float* be   = (const float*)d_in[6];
    const float* Wm   = (const float*)d_in[7];
    const float* bm   = (const float*)d_in[8];
    const float* beta = (const float*)d_in[9];

    const int N = in_sizes[0] / 128;
    const int E = in_sizes[2] / 64;

    detect_kernel<<<1, 32>>>(idx);
    prep_kernel<<<193, 128>>>(Wx, bx, We, be, Wm, bm);
    zero_kernel<<<512, 256>>>(N * OUT / 4);

    cudaFuncSetAttribute(node_kernel, cudaFuncAttributeMaxDynamicSharedMemorySize,
                         128 * 128 * (int)sizeof(float));
    node_kernel<<<148 * 3, 256, 128 * 128 * sizeof(float)>>>(x, N);

    edge_kernel<<<148 * 4, 256>>>(ea, idx, E);

    final_kernel<<<512, 256>>>((float*)d_out, beta, N * OUT / 4);
}